// round 11
// baseline (speedup 1.0000x reference)
#include <cuda_runtime.h>
#include <cuda_bf16.h>
#include <cstdint>

#define HH 256
#define WW 256
#define HW (HH * WW)

// Scratch (allocation-free rule: __device__ globals)
__device__ float g_p1[4 * 32 * HW];           // conv1 out
__device__ float g_p2[4 * 64 * HW];           // conv2 out
__device__ float g_pm[4 * 60 * HW];           // conv3 out (params)
__device__ float g_wB2[9 * 32 * 64 * 2];      // conv2 weights [c][kk][co][hi,lo]
__device__ float g_wB3[18 * 32 * 64 * 2];     // conv3 weights [c][kk][co][hi,lo]

// ---- tf32 helpers (non-arch-specific PTX, sm_80+) --------------------------
__device__ __forceinline__ unsigned tf32r(float v) {
    unsigned u;
    asm("cvt.rna.tf32.f32 %0, %1;" : "=r"(u) : "f"(v));
    return u;
}
__device__ __forceinline__ void split_tf32(float v, unsigned& hi, unsigned& lo) {
    hi = tf32r(v);
    lo = tf32r(v - __uint_as_float(hi));
}
__device__ __forceinline__ void mma_tf32(float* d, const unsigned* a, const unsigned* b) {
    asm volatile(
        "mma.sync.aligned.m16n8k8.row.col.f32.tf32.tf32.f32 "
        "{%0,%1,%2,%3}, {%4,%5,%6,%7}, {%8,%9}, {%0,%1,%2,%3};"
        : "+f"(d[0]), "+f"(d[1]), "+f"(d[2]), "+f"(d[3])
        : "r"(a[0]), "r"(a[1]), "r"(a[2]), "r"(a[3]), "r"(b[0]), "r"(b[1]));
}

// ---- cp.async helpers (sm_80+) ---------------------------------------------
__device__ __forceinline__ uint32_t smem_u32(const void* p) {
    uint32_t a;
    asm("{ .reg .u64 t; cvta.to.shared.u64 t, %1; cvt.u32.u64 %0, t; }" : "=r"(a) : "l"(p));
    return a;
}
#define CP_A4(dst, src, sz) \
    asm volatile("cp.async.ca.shared.global [%0], [%1], 4, %2;" :: "r"(dst), "l"(src), "r"(sz))
#define CP_A16(dst, src) \
    asm volatile("cp.async.ca.shared.global [%0], [%1], 16;" :: "r"(dst), "l"(src))
#define CP_COMMIT() asm volatile("cp.async.commit_group;" ::: "memory")
#define CP_WAIT1() asm volatile("cp.async.wait_group 1;" ::: "memory")
#define CP_WAIT0() asm volatile("cp.async.wait_group 0;" ::: "memory")

// ---------------------------------------------------------------------------
// Weight reorder: wt[cout][cin][9] -> out[c=j*G+g][kk(32)][co(64)][{hi,lo}]
// ---------------------------------------------------------------------------
__global__ void reorder_w(const float* __restrict__ wt, float* __restrict__ out,
                          int CIN, int COUT, int G) {
    int i = blockIdx.x * 256 + threadIdx.x;
    int total = 9 * G * 32 * 64;
    if (i >= total) return;
    int co = i & 63, kk = (i >> 6) & 31, c = i >> 11;
    int j = c / G, g = c % G;
    int ci = g * 32 + kk;
    float v = 0.f;
    if (co < COUT && ci < CIN) v = wt[((size_t)co * CIN + ci) * 9 + j];
    unsigned hi, lo;
    split_tf32(v, hi, lo);
    out[2 * i] = __uint_as_float(hi);
    out[2 * i + 1] = __uint_as_float(lo);
}

// ---------------------------------------------------------------------------
// 3xTF32 mma.sync implicit-GEMM 3x3 conv, v2:
//  - A in SMEM as raw fp32 (single copy), split hi/lo in regs at frag load
//  - B pre-split, SMEM (hi,lo) interleaved -> LDS.64 per b-frag element
//  - passes fused in one ks loop (ah reused against bh and bl)
//  - cp.async double-buffered prefetch (zero-fill OOB)
// CTA: 128px row-strip x 64 couts, 8 warps, warp = 32px x 32co.
// SMEM rows stride 136 words (=8 mod 32 -> conflict-free frag loads).
// ---------------------------------------------------------------------------
#define AS 136
#define BS 136
#define CONV_SMEM ((64 * AS + 64 * BS) * 4)   // 69632 B

template <int CIN, int COUT, bool RELU>
__global__ __launch_bounds__(256, 2)
void conv_tc(const float* __restrict__ in, const float* __restrict__ wBp,
             float* __restrict__ out) {
    constexpr int G = CIN / 32;
    constexpr int NCH = 9 * G;
    extern __shared__ float sm[];
    float* sA[2] = {sm, sm + 32 * AS};
    float* sB[2] = {sm + 64 * AS, sm + 64 * AS + 32 * BS};
    const uint32_t sAu[2] = {smem_u32(sA[0]), smem_u32(sA[1])};
    const uint32_t sBu[2] = {smem_u32(sB[0]), smem_u32(sB[1])};

    const int tid = threadIdx.x;
    const int wid = tid >> 5, lane = tid & 31;
    const int g = lane >> 2, t = lane & 3;
    const int pxb = (wid & 3) * 32;
    const int cob = (wid >> 2) * 32;
    const int x0 = blockIdx.x * 128, y = blockIdx.y, n = blockIdx.z;
    const float* in_n = in + (size_t)n * CIN * HW;

    const int pk = tid >> 3;   // 0..31 (k row for fills)
    const int pl = tid & 7;

    float acc[2][4][4];
#pragma unroll
    for (int mt = 0; mt < 2; mt++)
#pragma unroll
        for (int nt = 0; nt < 4; nt++)
#pragma unroll
            for (int e = 0; e < 4; e++) acc[mt][nt][e] = 0.f;

    auto fillA = [&](int c, int buf) {
        const int j = c / G, gg = c % G;
        const int dy = j / 3 - 1, dx = j % 3 - 1;
        const int yg = y + dy;
        const bool yok = (unsigned)yg < HH;
        const float* src = in_n + (size_t)(gg * 32 + pk) * HW + (size_t)(yok ? yg : 0) * WW;
        const uint32_t dst = sAu[buf] + (uint32_t)pk * (AS * 4);
#pragma unroll
        for (int i = 0; i < 16; i++) {
            const int px = pl + 8 * i;
            const int xg = x0 + px + dx;
            const unsigned ok = (yok && (unsigned)xg < WW) ? 4u : 0u;
            CP_A4(dst + px * 4, src + xg, ok);
        }
    };
    auto fillB = [&](int c, int buf) {
        const float* bsrc = wBp + (size_t)c * 4096 + pk * 128 + pl * 16;
        const uint32_t dst = sBu[buf] + (uint32_t)(pk * BS + pl * 16) * 4;
#pragma unroll
        for (int q = 0; q < 4; q++) CP_A16(dst + q * 16, bsrc + q * 4);
    };

    fillA(0, 0); fillB(0, 0); CP_COMMIT();
    fillA(1, 1); fillB(1, 1); CP_COMMIT();

    for (int c = 0; c < NCH; c++) {
        if (c + 1 < NCH) CP_WAIT1(); else CP_WAIT0();
        __syncthreads();

        const float* A = sA[c & 1];
        const float* B = sB[c & 1];

#pragma unroll
        for (int ks = 0; ks < 4; ks++) {
            const int kb = ks * 8;
            // B fragments: (hi,lo) pairs via 64-bit LDS, conflict-free per phase
            uint2 b0[4], b1[4];
#pragma unroll
            for (int nt = 0; nt < 4; nt++) {
                const int co = cob + nt * 8 + g;
                b0[nt] = *(const uint2*)&B[(kb + t) * BS + co * 2];
                b1[nt] = *(const uint2*)&B[(kb + t + 4) * BS + co * 2];
            }
            // A fragments: raw fp32, relu+split in regs
            unsigned ah[2][4], al[2][4];
#pragma unroll
            for (int mt = 0; mt < 2; mt++) {
                const int px = pxb + mt * 16 + g;
                float v0 = A[(kb + t) * AS + px];
                float v1 = A[(kb + t) * AS + px + 8];
                float v2 = A[(kb + t + 4) * AS + px];
                float v3 = A[(kb + t + 4) * AS + px + 8];
                if (RELU) {
                    v0 = fmaxf(v0, 0.f); v1 = fmaxf(v1, 0.f);
                    v2 = fmaxf(v2, 0.f); v3 = fmaxf(v3, 0.f);
                }
                split_tf32(v0, ah[mt][0], al[mt][0]);
                split_tf32(v1, ah[mt][1], al[mt][1]);
                split_tf32(v2, ah[mt][2], al[mt][2]);
                split_tf32(v3, ah[mt][3], al[mt][3]);
            }
#pragma unroll
            for (int nt = 0; nt < 4; nt++) {
                unsigned bh[2] = {b0[nt].x, b1[nt].x};
                unsigned bl[2] = {b0[nt].y, b1[nt].y};
#pragma unroll
                for (int mt = 0; mt < 2; mt++) {
                    mma_tf32(acc[mt][nt], ah[mt], bh);
                    mma_tf32(acc[mt][nt], al[mt], bh);
                    mma_tf32(acc[mt][nt], ah[mt], bl);
                }
            }
        }

        if (c + 2 < NCH) {
            __syncthreads();
            fillA(c + 2, c & 1);
            fillB(c + 2, c & 1);
            CP_COMMIT();
        }
    }

    // scatter store
    float* out_n = out + (size_t)n * COUT * HW + (size_t)y * WW + x0;
#pragma unroll
    for (int mt = 0; mt < 2; mt++)
#pragma unroll
        for (int nt = 0; nt < 4; nt++)
#pragma unroll
            for (int e = 0; e < 4; e++) {
                const int px = pxb + mt * 16 + g + ((e >> 1) & 1) * 8;
                const int co = cob + nt * 8 + 2 * t + (e & 1);
                if (co < COUT) out_n[(size_t)co * HW + px] = acc[mt][nt][e];
            }
}

// ---------------------------------------------------------------------------
// conv1 (10 -> 32): scalar fp32 direct conv
// ---------------------------------------------------------------------------
template <int CIN, int COUT, bool RELU>
__global__ __launch_bounds__(256, 2)
void conv3x3_kernel(const float* __restrict__ in, const float* __restrict__ wt,
                    float* __restrict__ out) {
    constexpr int CT = 16, CC = 4, TS = 32, IT = TS + 2;
    constexpr int BPC = (COUT + CT - 1) / CT;
    __shared__ float s_in[CC][IT][IT];
    __shared__ float s_w[CT][CC][9];
    const int tx = threadIdx.x, ty = threadIdx.y;
    const int tid = ty * 16 + tx;
    const int bx = blockIdx.x * TS, by = blockIdx.y * TS;
    const int cob = (blockIdx.z % BPC) * CT;
    const int n = blockIdx.z / BPC;
    const float* in_n = in + (size_t)n * CIN * HW;
    float acc[CT][2][2];
#pragma unroll
    for (int c = 0; c < CT; c++)
#pragma unroll
        for (int i = 0; i < 2; i++)
#pragma unroll
            for (int jj = 0; jj < 2; jj++) acc[c][i][jj] = 0.f;
    for (int c0 = 0; c0 < CIN; c0 += CC) {
        __syncthreads();
        for (int i = tid; i < CT * CC * 9; i += 256) {
            int ct = i / (CC * 9), rem = i - ct * (CC * 9);
            int cc = rem / 9, k = rem - cc * 9;
            int co = cob + ct, ci = c0 + cc;
            float v = 0.f;
            if (co < COUT && ci < CIN) v = wt[((size_t)co * CIN + ci) * 9 + k];
            s_w[ct][cc][k] = v;
        }
        for (int i = tid; i < CC * IT * IT; i += 256) {
            int cc = i / (IT * IT), rem = i - cc * (IT * IT);
            int r = rem / IT, cl = rem - r * IT;
            int ci = c0 + cc;
            int gy = by + r - 1, gx = bx + cl - 1;
            float v = 0.f;
            if (ci < CIN && (unsigned)gy < HH && (unsigned)gx < WW) {
                v = in_n[(size_t)ci * HW + gy * WW + gx];
                if (RELU) v = fmaxf(v, 0.f);
            }
            s_in[cc][r][cl] = v;
        }
        __syncthreads();
#pragma unroll
        for (int cc = 0; cc < CC; cc++) {
            float r[4][4];
#pragma unroll
            for (int i = 0; i < 4; i++)
#pragma unroll
                for (int jj = 0; jj < 4; jj++) r[i][jj] = s_in[cc][ty * 2 + i][tx * 2 + jj];
#pragma unroll
            for (int ct = 0; ct < CT; ct++) {
                float wk[9];
#pragma unroll
                for (int k = 0; k < 9; k++) wk[k] = s_w[ct][cc][k];
#pragma unroll
                for (int dy = 0; dy < 3; dy++)
#pragma unroll
                    for (int dx = 0; dx < 3; dx++) {
                        const float wv = wk[dy * 3 + dx];
                        acc[ct][0][0] = fmaf(wv, r[dy][dx], acc[ct][0][0]);
                        acc[ct][0][1] = fmaf(wv, r[dy][dx + 1], acc[ct][0][1]);
                        acc[ct][1][0] = fmaf(wv, r[dy + 1][dx], acc[ct][1][0]);
                        acc[ct][1][1] = fmaf(wv, r[dy + 1][dx + 1], acc[ct][1][1]);
                    }
            }
        }
    }
    const int oy = by + ty * 2, ox = bx + tx * 2;
#pragma unroll
    for (int ct = 0; ct < CT; ct++) {
        int co = cob + ct;
        if (co < COUT) {
            float* op = out + ((size_t)n * COUT + co) * HW + (size_t)oy * WW + ox;
            op[0] = acc[ct][0][0];
            op[1] = acc[ct][0][1];
            op[WW] = acc[ct][1][0];
            op[WW + 1] = acc[ct][1][1];
        }
    }
}

// ---------------------------------------------------------------------------
// Fused guide/PAC epilogue (unchanged)
// ---------------------------------------------------------------------------
__device__ __forceinline__ float softplus10(float p) {
    float z = 10.f * p;
    return (fmaxf(z, 0.f) + log1pf(__expf(-fabsf(z)))) * 0.1f;
}

__global__ __launch_bounds__(256)
void fuse_kernel(const float* __restrict__ x, const float* __restrict__ params,
                 const float* __restrict__ pw, const float* __restrict__ pb,
                 float* __restrict__ out) {
    const int gx = blockIdx.x * 32 + threadIdx.x;
    const int gy = blockIdx.y * 8 + threadIdx.y;
    const int z = blockIdx.z;
    const int j = z % 10, n = z / 10;
    const size_t opix = (((size_t)n * 10 + j) * HH + gy) * WW + gx;
    if (j == 9) { out[opix] = 0.f; return; }
    const int t = j + 1;
    const float* pbase = params + (size_t)n * 60 * HW + (size_t)gy * WW + gx;
    const float kap = softplus10(pbase[(size_t)(t) * HW]);
    const float m1d = pbase[(size_t)(10 + t) * HW];
    const float m2d = pbase[(size_t)(20 + t) * HW];
    const float gam = softplus10(pbase[(size_t)(30 + t) * HW]);
    const float vx = pbase[(size_t)(40 + t) * HW];
    const float vy = pbase[(size_t)(50 + t) * HW];
    const float H11 = gam + vx * vx;
    const float H22 = gam + vy * vy;
    const float H12 = vx * vy;
    const float iH11 = 1.f / H11;
    const float iH22 = 1.f / H22;
    float wk[9];
    wk[0] = -0.5f * H12;
    wk[1] = -iH22 + m1d;
    wk[2] = 0.5f * H12;
    wk[3] = -iH11 - m2d;
    wk[4] = kap + 2.f * H11 + 2.f * H22 + 1.f;
    wk[5] = -iH11 + m2d;
    wk[6] = 0.5f * H12;
    wk[7] = -iH22 - m1d;
    wk[8] = -0.5f * H12;
    const float* xf = x + ((size_t)n * 10 + t) * HW;
    float s = 0.f;
#pragma unroll
    for (int d = 0; d < 3; d++)
#pragma unroll
        for (int e = 0; e < 3; e++) {
            const int yy = gy + d - 1, xx = gx + e - 1;
            float xv = 0.f;
            if ((unsigned)yy < HH && (unsigned)xx < WW) xv = __ldg(xf + (size_t)yy * WW + xx);
            s = fmaf(__ldg(pw + d * 3 + e) * wk[d * 3 + e], xv, s);
        }
    out[opix] = s + __ldg(pb);
}

extern "C" void kernel_launch(void* const* d_in, const int* in_sizes, int n_in,
                              void* d_out, int out_size) {
    (void)in_sizes; (void)n_in; (void)out_size;
    const float* x  = (const float*)d_in[0];
    const float* w1 = (const float*)d_in[1];
    const float* w2 = (const float*)d_in[2];
    const float* w3 = (const float*)d_in[3];
    const float* pw = (const float*)d_in[4];
    const float* pb = (const float*)d_in[5];
    float* out = (float*)d_out;

    float *p1, *p2, *pm, *wB2, *wB3;
    cudaGetSymbolAddress((void**)&p1, g_p1);
    cudaGetSymbolAddress((void**)&p2, g_p2);
    cudaGetSymbolAddress((void**)&pm, g_pm);
    cudaGetSymbolAddress((void**)&wB2, g_wB2);
    cudaGetSymbolAddress((void**)&wB3, g_wB3);

    cudaFuncSetAttribute(conv_tc<32, 64, true>,
                         cudaFuncAttributeMaxDynamicSharedMemorySize, CONV_SMEM);
    cudaFuncSetAttribute(conv_tc<64, 60, false>,
                         cudaFuncAttributeMaxDynamicSharedMemorySize, CONV_SMEM);

    // weight reorders + hi/lo pre-split (tiny)
    reorder_w<<<(9 * 2048 + 255) / 256, 256>>>(w2, wB2, 32, 64, 1);
    reorder_w<<<(18 * 2048 + 255) / 256, 256>>>(w3, wB3, 64, 60, 2);

    // conv1: 10 -> 32, scalar fp32
    conv3x3_kernel<10, 32, true><<<dim3(8, 8, 4 * 2), dim3(16, 16)>>>(x, w1, p1);
    // conv2: 32 -> 64, 3xTF32 mma.sync (relu on input)
    conv_tc<32, 64, true><<<dim3(2, 256, 4), 256, CONV_SMEM>>>(p1, wB2, p2);
    // conv3: 64 -> 60, 3xTF32 mma.sync
    conv_tc<64, 60, false><<<dim3(2, 256, 4), 256, CONV_SMEM>>>(p2, wB3, pm);
    // fused guide + PAC epilogue (also zeroes frame 9)
    fuse_kernel<<<dim3(8, 32, 40), dim3(32, 8)>>>(x, pm, pw, pb, out);
}